// round 1
// baseline (speedup 1.0000x reference)
#include <cuda_runtime.h>
#include <math.h>

#define T_SEQ  2048
#define BATCH  4
#define NH     16
#define DH     64
#define RANK   32
#define DM     1024
#define M_TOK  (BATCH * T_SEQ)   // 8192
#define NQKV   2048               // 512 q_lr | 512 k_lr | 1024 v

// ---------------- scratch (device globals; no allocs allowed) ----------------
__device__ float g_Weff[(size_t)NQKV * DM];       // 8 MB
__device__ float g_beff[NQKV];
__device__ float g_qkv [(size_t)M_TOK * NQKV];    // 64 MB
__device__ float g_y   [(size_t)M_TOK * DM];      // 32 MB

// ---------------- kernel 1: build effective fused weights --------------------
// rows [0,512):   Wq_eff[h*32+r][d] = sum_e Wq[h*64+e][d] * Wq_lsr[h][e][r]
// rows [512,1024): same with Wk / Wk_lsr
// rows [1024,2048): copy of Wv
__global__ void build_eff(const float* __restrict__ Wq, const float* __restrict__ bq,
                          const float* __restrict__ Wk, const float* __restrict__ bk,
                          const float* __restrict__ Wv, const float* __restrict__ bv,
                          const float* __restrict__ Wq_lsr, const float* __restrict__ Wk_lsr)
{
    int row = blockIdx.x;
    int tid = threadIdx.x;  // 256 threads

    if (row >= 1024) {
        int o = row - 1024;
        const float* src = Wv + (size_t)o * DM;
        float* dst = g_Weff + (size_t)row * DM;
        for (int d = tid; d < DM; d += 256) dst[d] = src[d];
        if (tid == 0) g_beff[row] = bv[o];
        return;
    }

    const float* W   = (row < 512) ? Wq : Wk;
    const float* bb  = (row < 512) ? bq : bk;
    const float* lsr = (row < 512) ? Wq_lsr : Wk_lsr;
    int rr = row & 511;
    int h  = rr >> 5;
    int r  = rr & 31;

    __shared__ float lcol[DH];
    if (tid < DH) lcol[tid] = lsr[(h * DH + tid) * RANK + r];
    __syncthreads();

    float* dst = g_Weff + (size_t)row * DM;
    for (int d = tid; d < DM; d += 256) {
        float s = 0.f;
        #pragma unroll
        for (int e = 0; e < DH; ++e)
            s += W[(size_t)(h * DH + e) * DM + d] * lcol[e];
        dst[d] = s;
    }
    if (tid == 0) {
        float s = 0.f;
        #pragma unroll
        for (int e = 0; e < DH; ++e) s += bb[h * DH + e] * lcol[e];
        g_beff[row] = s;
    }
}

// ---------------- kernel 2/4: C(MxN) = A(MxK) @ B(NxK)^T + bias --------------
// 128x128 block tile, BK=16, 256 threads, 8x8 per-thread microtile.
__global__ __launch_bounds__(256)
void sgemm_nt(const float* __restrict__ A, const float* __restrict__ B,
              const float* __restrict__ bias, float* __restrict__ C,
              int M, int N, int K)
{
    __shared__ float As[16][128];
    __shared__ float Bs[16][128];

    const int bm  = blockIdx.y * 128;
    const int bn  = blockIdx.x * 128;
    const int tid = threadIdx.x;
    const int ty  = tid >> 4;   // 0..15
    const int tx  = tid & 15;   // 0..15

    const float* Ab = A + (size_t)bm * K;
    const float* Bb = B + (size_t)bn * K;

    float acc[8][8];
    #pragma unroll
    for (int i = 0; i < 8; ++i)
        #pragma unroll
        for (int j = 0; j < 8; ++j) acc[i][j] = 0.f;

    for (int k0 = 0; k0 < K; k0 += 16) {
        #pragma unroll
        for (int i = 0; i < 2; ++i) {
            int idx = tid + i * 256;           // [0,512)
            int row = idx >> 2;                // [0,128)
            int kc  = (idx & 3) * 4;           // {0,4,8,12}
            float4 a = *(const float4*)(Ab + (size_t)row * K + k0 + kc);
            As[kc + 0][row] = a.x; As[kc + 1][row] = a.y;
            As[kc + 2][row] = a.z; As[kc + 3][row] = a.w;
            float4 b = *(const float4*)(Bb + (size_t)row * K + k0 + kc);
            Bs[kc + 0][row] = b.x; Bs[kc + 1][row] = b.y;
            Bs[kc + 2][row] = b.z; Bs[kc + 3][row] = b.w;
        }
        __syncthreads();

        #pragma unroll
        for (int kk = 0; kk < 16; ++kk) {
            float af[8], bf[8];
            *(float4*)(af    ) = *(const float4*)(&As[kk][ty * 8    ]);
            *(float4*)(af + 4) = *(const float4*)(&As[kk][ty * 8 + 4]);
            *(float4*)(bf    ) = *(const float4*)(&Bs[kk][tx * 8    ]);
            *(float4*)(bf + 4) = *(const float4*)(&Bs[kk][tx * 8 + 4]);
            #pragma unroll
            for (int i = 0; i < 8; ++i)
                #pragma unroll
                for (int j = 0; j < 8; ++j)
                    acc[i][j] += af[i] * bf[j];
        }
        __syncthreads();
    }

    float bl[8];
    #pragma unroll
    for (int j = 0; j < 8; ++j) bl[j] = bias[bn + tx * 8 + j];

    #pragma unroll
    for (int i = 0; i < 8; ++i) {
        float* cp = C + (size_t)(bm + ty * 8 + i) * N + bn + tx * 8;
        float4 o0 = make_float4(acc[i][0] + bl[0], acc[i][1] + bl[1],
                                acc[i][2] + bl[2], acc[i][3] + bl[3]);
        float4 o1 = make_float4(acc[i][4] + bl[4], acc[i][5] + bl[5],
                                acc[i][6] + bl[6], acc[i][7] + bl[7]);
        *(float4*)(cp)     = o0;
        *(float4*)(cp + 4) = o1;
    }
}

// ---------------- kernel 3: causal flash attention (rank-32 scores) ----------
// grid: (T/128, B*H), 128 threads; thread owns one query row.
__global__ __launch_bounds__(128)
void attn_kernel()
{
    const int bh    = blockIdx.y;
    const int b     = bh >> 4;
    const int h     = bh & 15;
    const int qbase = blockIdx.x * 128;
    const int tid   = threadIdx.x;
    const int qrow  = qbase + tid;

    // fold softmax scale and log2(e) into q
    const float qscale = 1.44269504088896f * (1.0f / sqrtf((float)RANK));

    __shared__ float k_sh[64][32];
    __shared__ float v_sh[64][64];

    const float* qp = g_qkv + ((size_t)(b * T_SEQ + qrow)) * NQKV + h * RANK;
    float qv[32];
    #pragma unroll
    for (int r = 0; r < 32; r += 4) {
        float4 t = *(const float4*)(qp + r);
        qv[r]     = t.x * qscale;
        qv[r + 1] = t.y * qscale;
        qv[r + 2] = t.z * qscale;
        qv[r + 3] = t.w * qscale;
    }

    float acc[64];
    #pragma unroll
    for (int e = 0; e < 64; ++e) acc[e] = 0.f;
    float m = -INFINITY;
    float l = 0.f;

    const int jend = qbase + 128;     // causal: keys < qbase+128 suffice
    const int jr   = tid >> 1;        // tile row this thread loads
    const int part = tid & 1;

    for (int j0 = 0; j0 < jend; j0 += 64) {
        // cooperative tile load: 2 threads per key row
        const float* kp = g_qkv + ((size_t)(b * T_SEQ + j0 + jr)) * NQKV + 512 + h * RANK + part * 16;
        float4* kd = (float4*)(&k_sh[jr][part * 16]);
        #pragma unroll
        for (int i = 0; i < 4; ++i) kd[i] = ((const float4*)kp)[i];

        const float* vp = g_qkv + ((size_t)(b * T_SEQ + j0 + jr)) * NQKV + 1024 + h * DH + part * 32;
        float4* vd = (float4*)(&v_sh[jr][part * 32]);
        #pragma unroll
        for (int i = 0; i < 8; ++i) vd[i] = ((const float4*)vp)[i];
        __syncthreads();

        int jmax = qrow - j0 + 1;
        if (jmax > 64) jmax = 64;
        for (int jj = 0; jj < jmax; ++jj) {
            const float4* kk4 = (const float4*)k_sh[jj];
            float s = 0.f;
            #pragma unroll
            for (int r = 0; r < 8; ++r) {
                float4 kk = kk4[r];
                s += qv[4 * r]     * kk.x;
                s += qv[4 * r + 1] * kk.y;
                s += qv[4 * r + 2] * kk.z;
                s += qv[4 * r + 3] * kk.w;
            }
            if (s > m) {                      // rare rescale path
                float corr = exp2f(m - s);    // m=-inf on first key -> corr=0
                m = s;
                l *= corr;
                #pragma unroll
                for (int e = 0; e < 64; ++e) acc[e] *= corr;
            }
            float p = exp2f(s - m);
            l += p;
            const float4* vv4 = (const float4*)v_sh[jj];
            #pragma unroll
            for (int e = 0; e < 16; ++e) {
                float4 vv = vv4[e];
                acc[4 * e]     += p * vv.x;
                acc[4 * e + 1] += p * vv.y;
                acc[4 * e + 2] += p * vv.z;
                acc[4 * e + 3] += p * vv.w;
            }
        }
        __syncthreads();
    }

    const float inv = 1.f / l;
    float* yp = g_y + ((size_t)(b * T_SEQ + qrow)) * DM + h * DH;
    #pragma unroll
    for (int e = 0; e < 64; e += 4) {
        float4 o = make_float4(acc[e] * inv, acc[e + 1] * inv,
                               acc[e + 2] * inv, acc[e + 3] * inv);
        *(float4*)(yp + e) = o;
    }
}

// ---------------- launch ----------------
extern "C" void kernel_launch(void* const* d_in, const int* in_sizes, int n_in,
                              void* d_out, int out_size)
{
    const float* x      = (const float*)d_in[0];
    const float* Wq     = (const float*)d_in[1];
    const float* bq     = (const float*)d_in[2];
    const float* Wk     = (const float*)d_in[3];
    const float* bk     = (const float*)d_in[4];
    const float* Wv     = (const float*)d_in[5];
    const float* bv     = (const float*)d_in[6];
    const float* Wo     = (const float*)d_in[7];
    const float* bo     = (const float*)d_in[8];
    const float* Wq_lsr = (const float*)d_in[9];
    const float* Wk_lsr = (const float*)d_in[10];
    float* out = (float*)d_out;

    float *pWeff, *pbeff, *pqkv, *py;
    cudaGetSymbolAddress((void**)&pWeff, g_Weff);
    cudaGetSymbolAddress((void**)&pbeff, g_beff);
    cudaGetSymbolAddress((void**)&pqkv,  g_qkv);
    cudaGetSymbolAddress((void**)&py,    g_y);

    // 1) fused effective weights [Wq_eff | Wk_eff | Wv]
    build_eff<<<NQKV, 256>>>(Wq, bq, Wk, bk, Wv, bv, Wq_lsr, Wk_lsr);

    // 2) qkv = x @ Weff^T + beff   (8192 x 2048 x 1024)
    sgemm_nt<<<dim3(NQKV / 128, M_TOK / 128), 256>>>(x, pWeff, pbeff, pqkv,
                                                     M_TOK, NQKV, DM);

    // 3) causal attention -> y
    attn_kernel<<<dim3(T_SEQ / 128, BATCH * NH), 128>>>();

    // 4) out = y @ Wo^T + bo       (8192 x 1024 x 1024)
    sgemm_nt<<<dim3(DM / 128, M_TOK / 128), 256>>>(py, Wo, bo, out,
                                                   M_TOK, DM, DM);
}

// round 3
// speedup vs baseline: 1.2718x; 1.2718x over previous
#include <cuda_runtime.h>
#include <cuda_bf16.h>
#include <math.h>
#include <stdint.h>

#define T_SEQ  2048
#define BATCH  4
#define NH     16
#define DH     64
#define RANK   32
#define DM     1024
#define M_TOK  (BATCH * T_SEQ)   // 8192
#define NQKV   2048               // 512 q_lr | 512 k_lr | 1024 v
#define K3     (3 * DM)           // 3072 virtual K (hi/lo/hi split)
#define KCH    32                 // K per mainloop iter (bf16 elems)
#define NCH    (K3 / KCH)         // 96

// ---------------- scratch (device globals; no allocs allowed) ----------------
__device__ float          g_Weff[(size_t)NQKV * DM];     // 8 MB
__device__ float          g_beff[NQKV];
__device__ float          g_qkv [(size_t)M_TOK * NQKV];  // 64 MB
__device__ float          g_y   [(size_t)M_TOK * DM];    // 32 MB
__device__ __nv_bfloat16  g_a3  [(size_t)M_TOK * K3];    // 48 MB (x3, then y3)
__device__ __nv_bfloat16  g_b3  [(size_t)NQKV  * K3];    // 12 MB (Weff3, then Wo3)

// ============================ helpers ========================================
__device__ __forceinline__ uint32_t smem_to_u32(const void* p) {
    uint32_t a;
    asm("{ .reg .u64 t; cvta.to.shared.u64 t, %1; cvt.u32.u64 %0, t; }"
        : "=r"(a) : "l"(p));
    return a;
}
#define SW128(off) ((off) ^ (((off) >> 3) & 0x70))

#define LDMX4(r0, r1, r2, r3, addr) \
    asm volatile("ldmatrix.sync.aligned.m8n8.x4.shared.b16 {%0,%1,%2,%3}, [%4];" \
        : "=r"(r0), "=r"(r1), "=r"(r2), "=r"(r3) : "r"(addr))

#define MMA16816(c, a, b) \
    asm volatile("mma.sync.aligned.m16n8k16.row.col.f32.bf16.bf16.f32 " \
        "{%0,%1,%2,%3}, {%4,%5,%6,%7}, {%8,%9}, {%0,%1,%2,%3};" \
        : "+f"((c)[0]), "+f"((c)[1]), "+f"((c)[2]), "+f"((c)[3]) \
        : "r"((a)[0]), "r"((a)[1]), "r"((a)[2]), "r"((a)[3]), \
          "r"((b)[0]), "r"((b)[1]))

// ---------------- kernel 1: build effective fused weights --------------------
__global__ void build_eff(const float* __restrict__ Wq, const float* __restrict__ bq,
                          const float* __restrict__ Wk, const float* __restrict__ bk,
                          const float* __restrict__ Wv, const float* __restrict__ bv,
                          const float* __restrict__ Wq_lsr, const float* __restrict__ Wk_lsr)
{
    int row = blockIdx.x;
    int tid = threadIdx.x;  // 256 threads

    if (row >= 1024) {
        int o = row - 1024;
        const float* src = Wv + (size_t)o * DM;
        float* dst = g_Weff + (size_t)row * DM;
        for (int d = tid; d < DM; d += 256) dst[d] = src[d];
        if (tid == 0) g_beff[row] = bv[o];
        return;
    }

    const float* W   = (row < 512) ? Wq : Wk;
    const float* bb  = (row < 512) ? bq : bk;
    const float* lsr = (row < 512) ? Wq_lsr : Wk_lsr;
    int rr = row & 511;
    int h  = rr >> 5;
    int r  = rr & 31;

    __shared__ float lcol[DH];
    if (tid < DH) lcol[tid] = lsr[(h * DH + tid) * RANK + r];
    __syncthreads();

    float* dst = g_Weff + (size_t)row * DM;
    for (int d = tid; d < DM; d += 256) {
        float s = 0.f;
        #pragma unroll
        for (int e = 0; e < DH; ++e)
            s += W[(size_t)(h * DH + e) * DM + d] * lcol[e];
        dst[d] = s;
    }
    if (tid == 0) {
        float s = 0.f;
        #pragma unroll
        for (int e = 0; e < DH; ++e) s += bb[h * DH + e] * lcol[e];
        g_beff[row] = s;
    }
}

// ---------------- split fp32 row (1024) -> bf16 row (3072) -------------------
// pattern 0 (activations): [hi | lo | hi]; pattern 1 (weights): [hi | hi | lo]
__global__ __launch_bounds__(256)
void split3(const float* __restrict__ in, __nv_bfloat16* __restrict__ out, int pattern)
{
    int row = blockIdx.x;
    int tid = threadIdx.x;
    const float* ip = in + (size_t)row * DM;
    __nv_bfloat16* op = out + (size_t)row * K3;
    for (int d = tid; d < DM; d += 256) {
        float v = ip[d];
        __nv_bfloat16 hi = __float2bfloat16(v);
        __nv_bfloat16 lo = __float2bfloat16(v - __bfloat162float(hi));
        op[d] = hi;
        op[DM + d]     = pattern ? hi : lo;
        op[2 * DM + d] = pattern ? lo : hi;
    }
}

// ---------------- HMMA bf16 GEMM: C(MxN) = A3(MxK3) @ B3(NxK3)^T + bias ------
// 128x128 CTA tile, 8 warps (2M x 4N), warp tile 64x32, BK=32, double buffer.
__global__ __launch_bounds__(256)
void gemm_bf16_hmma(const __nv_bfloat16* __restrict__ A,
                    const __nv_bfloat16* __restrict__ B,
                    const float* __restrict__ bias,
                    float* __restrict__ C, int N)
{
    // [stage][A=0/B=1][128 rows x 32 bf16, SW128-swizzled 64B rows]
    __shared__ __align__(128) char sm_tiles[2][2][8192];
    const uint32_t s_base = smem_to_u32(sm_tiles);

    const int tid  = threadIdx.x;
    const int lane = tid & 31;
    const int wid  = tid >> 5;
    const int wm   = wid >> 2;   // 0..1
    const int wn   = wid & 3;    // 0..3
    const int bm   = blockIdx.y * 128;
    const int bn   = blockIdx.x * 128;

    const __nv_bfloat16* Ab = A + (size_t)bm * K3;
    const __nv_bfloat16* Bb = B + (size_t)bn * K3;

    // global staging map: thread covers 32B of one row per tile
    const int grow = tid >> 1;            // [0,128)
    const int gseg = (tid & 1) * 2;       // {0,2} : 16B segments
    const uint32_t sw0 = SW128((uint32_t)(grow * 64 + gseg * 16));
    const uint32_t sw1 = SW128((uint32_t)(grow * 64 + gseg * 16 + 16));
    const __nv_bfloat16* gA = Ab + (size_t)grow * K3 + gseg * 8;
    const __nv_bfloat16* gB = Bb + (size_t)grow * K3 + gseg * 8;

    // ldmatrix per-lane swizzled offsets
    uint32_t aoff[4][2], boff[2][2];
    #pragma unroll
    for (int f = 0; f < 4; ++f)
        #pragma unroll
        for (int ks = 0; ks < 2; ++ks)
            aoff[f][ks] = SW128((uint32_t)((wm * 64 + f * 16 + (lane & 15)) * 64 +
                                           (ks * 2 + (lane >> 4)) * 16));
    #pragma unroll
    for (int p = 0; p < 2; ++p)
        #pragma unroll
        for (int ks = 0; ks < 2; ++ks)
            boff[p][ks] = SW128((uint32_t)((wn * 32 + p * 16 + ((lane >> 4) & 1) * 8 +
                                            (lane & 7)) * 64 +
                                           (ks * 2 + ((lane >> 3) & 1)) * 16));

    float acc[4][4][4];
    #pragma unroll
    for (int f = 0; f < 4; ++f)
        #pragma unroll
        for (int nf = 0; nf < 4; ++nf)
            #pragma unroll
            for (int i = 0; i < 4; ++i) acc[f][nf][i] = 0.f;

    // prologue: load chunk 0 into stage 0
    {
        uint4 a0 = *(const uint4*)(gA);
        uint4 a1 = *(const uint4*)(gA + 8);
        uint4 b0 = *(const uint4*)(gB);
        uint4 b1 = *(const uint4*)(gB + 8);
        char* sA = &sm_tiles[0][0][0];
        char* sB = &sm_tiles[0][1][0];
        *(uint4*)(sA + sw0) = a0; *(uint4*)(sA + sw1) = a1;
        *(uint4*)(sB + sw0) = b0; *(uint4*)(sB + sw1) = b1;
    }
    __syncthreads();

    for (int c = 0; c < NCH; ++c) {
        const int stg = c & 1;
        uint4 pa0, pa1, pb0, pb1;
        if (c + 1 < NCH) {
            const int ko = (c + 1) * KCH;
            pa0 = *(const uint4*)(gA + ko);
            pa1 = *(const uint4*)(gA + ko + 8);
            pb0 = *(const uint4*)(gB + ko);
            pb1 = *(const uint4*)(gB + ko + 8);
        }

        const uint32_t As = s_base + (uint32_t)stg * 16384u;
        const uint32_t Bs = As + 8192u;
        #pragma unroll
        for (int ks = 0; ks < 2; ++ks) {
            uint32_t a[4][4];
            #pragma unroll
            for (int f = 0; f < 4; ++f)
                LDMX4(a[f][0], a[f][1], a[f][2], a[f][3], As + aoff[f][ks]);
            uint32_t b[4][2];
            #pragma unroll
            for (int p = 0; p < 2; ++p)
                LDMX4(b[2 * p][0], b[2 * p][1], b[2 * p + 1][0], b[2 * p + 1][1],
                      Bs + boff[p][ks]);
            #pragma unroll
            for (int f = 0; f < 4; ++f)
                #pragma unroll
                for (int nf = 0; nf < 4; ++nf)
                    MMA16816(acc[f][nf], a[f], b[nf]);
        }

        if (c + 1 < NCH) {
            char* sA = &sm_tiles[(c + 1) & 1][0][0];
            char* sB = &sm_tiles[(c + 1) & 1][1][0];
            *(uint4*)(sA + sw0) = pa0; *(uint4*)(sA + sw1) = pa1;
            *(uint4*)(sB + sw0) = pb0; *(uint4*)(sB + sw1) = pb1;
        }
        __syncthreads();
    }

    // epilogue: bias + store (c0,c1)->(row,col..col+1), (c2,c3)->(row+8,...)
    const int col0 = bn + wn * 32 + (lane & 3) * 2;
    float2 blv[4];
    #pragma unroll
    for (int nf = 0; nf < 4; ++nf) {
        blv[nf].x = bias[col0 + nf * 8];
        blv[nf].y = bias[col0 + nf * 8 + 1];
    }
    #pragma unroll
    for (int f = 0; f < 4; ++f) {
        const int row = bm + wm * 64 + f * 16 + (lane >> 2);
        #pragma unroll
        for (int nf = 0; nf < 4; ++nf) {
            const int col = col0 + nf * 8;
            float2 o0 = make_float2(acc[f][nf][0] + blv[nf].x,
                                    acc[f][nf][1] + blv[nf].y);
            float2 o1 = make_float2(acc[f][nf][2] + blv[nf].x,
                                    acc[f][nf][3] + blv[nf].y);
            *(float2*)(C + (size_t)row * N + col)       = o0;
            *(float2*)(C + (size_t)(row + 8) * N + col) = o1;
        }
    }
}

// ---------------- kernel 3: causal flash attention (rank-32 scores) ----------
__global__ __launch_bounds__(128)
void attn_kernel()
{
    const int bh    = blockIdx.y;
    const int b     = bh >> 4;
    const int h     = bh & 15;
    const int qbase = blockIdx.x * 128;
    const int tid   = threadIdx.x;
    const int qrow  = qbase + tid;

    const float qscale = 1.44269504088896f * (1.0f / sqrtf((float)RANK));

    __shared__ float k_sh[64][32];
    __shared__ float v_sh[64][64];

    const float* qp = g_qkv + ((size_t)(b * T_SEQ + qrow)) * NQKV + h * RANK;
    float qv[32];
    #pragma unroll
    for (int r = 0; r < 32; r += 4) {
        float4 t = *(const float4*)(qp + r);
        qv[r]     = t.x * qscale;
        qv[r + 1] = t.y * qscale;
        qv[r + 2] = t.z * qscale;
        qv[r + 3] = t.w * qscale;
    }

    float acc[64];
    #pragma unroll
    for (int e = 0; e < 64; ++e) acc[e] = 0.f;
    float m = -INFINITY;
    float l = 0.f;

    const int jend = qbase + 128;
    const int jr   = tid >> 1;
    const int part = tid & 1;

    for (int j0 = 0; j0 < jend; j0 += 64) {
        const float* kp = g_qkv + ((size_t)(b * T_SEQ + j0 + jr)) * NQKV + 512 + h * RANK + part * 16;
        float4* kd = (float4*)(&k_sh[jr][part * 16]);
        #pragma unroll
        for (int i = 0; i < 4; ++i) kd[i] = ((const float4*)kp)[i];

        const float* vp = g_qkv + ((size_t)(b * T_SEQ + j0 + jr)) * NQKV + 1024 + h * DH + part * 32;
        float4* vd = (float4*)(&v_sh[jr][part * 32]);
        #pragma unroll
        for (int i = 0; i < 8; ++i) vd[i] = ((const float4*)vp)[i];
        __syncthreads();

        int jmax = qrow - j0 + 1;
        if (jmax > 64) jmax = 64;
        for (int jj = 0; jj < jmax; ++jj) {
            const float4* kk4 = (const float4*)k_sh[jj];
            float s = 0.f;
            #pragma unroll
            for (int r = 0; r < 8; ++r) {
                float4 kk = kk4[r];
                s += qv[4 * r]     * kk.x;
                s += qv[4 * r + 1] * kk.y;
                s += qv[4 * r + 2] * kk.z;
                s += qv[4 * r + 3] * kk.w;
            }
            if (s > m) {
                float corr = exp2f(m - s);
                m = s;
                l *= corr;
                #pragma unroll
                for (int e = 0; e < 64; ++e) acc[e] *= corr;
            }
            float p = exp2f(s - m);
            l += p;
            const float4* vv4 = (const float4*)v_sh[jj];
            #pragma unroll
            for (int e = 0; e < 16; ++e) {
                float4 vv = vv4[e];
                acc[4 * e]     += p * vv.x;
                acc[4 * e + 1] += p * vv.y;
                acc[4 * e + 2] += p * vv.z;
                acc[4 * e + 3] += p * vv.w;
            }
        }
        __syncthreads();
    }

    const float inv = 1.f / l;
    float* yp = g_y + ((size_t)(b * T_SEQ + qrow)) * DM + h * DH;
    #pragma unroll
    for (int e = 0; e < 64; e += 4) {
        float4 o = make_float4(acc[e] * inv, acc[e + 1] * inv,
                               acc[e + 2] * inv, acc[e + 3] * inv);
        *(float4*)(yp + e) = o;
    }
}

// ---------------- launch ----------------
extern "C" void kernel_launch(void* const* d_in, const int* in_sizes, int n_in,
                              void* d_out, int out_size)
{
    const float* x      = (const float*)d_in[0];
    const float* Wq     = (const float*)d_in[1];
    const float* bq     = (const float*)d_in[2];
    const float* Wk     = (const float*)d_in[3];
    const float* bk     = (const float*)d_in[4];
    const float* Wv     = (const float*)d_in[5];
    const float* bv     = (const float*)d_in[6];
    const float* Wo     = (const float*)d_in[7];
    const float* bo     = (const float*)d_in[8];
    const float* Wq_lsr = (const float*)d_in[9];
    const float* Wk_lsr = (const float*)d_in[10];
    float* out = (float*)d_out;

    float *pWeff, *pbeff, *pqkv, *py;
    __nv_bfloat16 *pa3, *pb3;
    cudaGetSymbolAddress((void**)&pWeff, g_Weff);
    cudaGetSymbolAddress((void**)&pbeff, g_beff);
    cudaGetSymbolAddress((void**)&pqkv,  g_qkv);
    cudaGetSymbolAddress((void**)&py,    g_y);
    cudaGetSymbolAddress((void**)&pa3,   g_a3);
    cudaGetSymbolAddress((void**)&pb3,   g_b3);

    // 1) fused effective weights [Wq_eff | Wk_eff | Wv]
    build_eff<<<NQKV, 256>>>(Wq, bq, Wk, bk, Wv, bv, Wq_lsr, Wk_lsr);

    // 2) splits for qkv GEMM
    split3<<<M_TOK, 256>>>(x, pa3, 0);
    split3<<<NQKV, 256>>>(pWeff, pb3, 1);

    // 3) qkv = x @ Weff^T + beff (HMMA bf16 3x)
    gemm_bf16_hmma<<<dim3(NQKV / 128, M_TOK / 128), 256>>>(pa3, pb3, pbeff, pqkv, NQKV);

    // 4) causal attention -> y
    attn_kernel<<<dim3(T_SEQ / 128, BATCH * NH), 128>>>();

    // 5) splits for out GEMM (reuse scratch)
    split3<<<M_TOK, 256>>>(py, pa3, 0);
    split3<<<DM, 256>>>(Wo, pb3, 1);

    // 6) out = y @ Wo^T + bo (HMMA bf16 3x)
    gemm_bf16_hmma<<<dim3(DM / 128, M_TOK / 128), 256>>>(pa3, pb3, bo, out, DM);
}

// round 4
// speedup vs baseline: 2.5680x; 2.0192x over previous
#include <cuda_runtime.h>
#include <cuda_bf16.h>
#include <math.h>
#include <stdint.h>

#define T_SEQ  2048
#define BATCH  4
#define NH     16
#define DH     64
#define RANK   32
#define DM     1024
#define M_TOK  (BATCH * T_SEQ)   // 8192
#define NQKV   2048               // 512 q_lr | 512 k_lr | 1024 v
#define K3     (3 * DM)           // 3072 virtual K (hi/lo/hi split)
#define KCH    32                 // GEMM K per mainloop iter
#define NCH    (K3 / KCH)         // 96

// ---------------- scratch (device globals; no allocs allowed) ----------------
__device__ float          g_Weff[(size_t)NQKV * DM];     // 8 MB
__device__ float          g_beff[NQKV];
__device__ float          g_qkv [(size_t)M_TOK * NQKV];  // 64 MB
__device__ __nv_bfloat16  g_a3  [(size_t)M_TOK * K3];    // 48 MB (x3, then y3)
__device__ __nv_bfloat16  g_b3  [(size_t)NQKV  * K3];    // 12 MB (Weff3, then Wo3)
// attention split operands, [bh][t][64] each (16 MB each)
__device__ __nv_bfloat16  g_q2 [(size_t)64 * T_SEQ * 64];
__device__ __nv_bfloat16  g_k2 [(size_t)64 * T_SEQ * 64];
__device__ __nv_bfloat16  g_vh [(size_t)64 * T_SEQ * 64];
__device__ __nv_bfloat16  g_vl [(size_t)64 * T_SEQ * 64];

// ============================ helpers ========================================
__device__ __forceinline__ uint32_t smem_to_u32(const void* p) {
    uint32_t a;
    asm("{ .reg .u64 t; cvta.to.shared.u64 t, %1; cvt.u32.u64 %0, t; }"
        : "=r"(a) : "l"(p));
    return a;
}
#define SW128(off) ((off) ^ (((off) >> 3) & 0x70))

#define LDMX4(r0, r1, r2, r3, addr) \
    asm volatile("ldmatrix.sync.aligned.m8n8.x4.shared.b16 {%0,%1,%2,%3}, [%4];" \
        : "=r"(r0), "=r"(r1), "=r"(r2), "=r"(r3) : "r"(addr))

#define LDMX4T(r0, r1, r2, r3, addr) \
    asm volatile("ldmatrix.sync.aligned.m8n8.x4.trans.shared.b16 {%0,%1,%2,%3}, [%4];" \
        : "=r"(r0), "=r"(r1), "=r"(r2), "=r"(r3) : "r"(addr))

#define MMA16816(c, a, b) \
    asm volatile("mma.sync.aligned.m16n8k16.row.col.f32.bf16.bf16.f32 " \
        "{%0,%1,%2,%3}, {%4,%5,%6,%7}, {%8,%9}, {%0,%1,%2,%3};" \
        : "+f"((c)[0]), "+f"((c)[1]), "+f"((c)[2]), "+f"((c)[3]) \
        : "r"((a)[0]), "r"((a)[1]), "r"((a)[2]), "r"((a)[3]), \
          "r"((b)[0]), "r"((b)[1]))

#define CP16(dst, src) \
    asm volatile("cp.async.cg.shared.global [%0], [%1], 16;" :: "r"(dst), "l"(src))
#define CP_COMMIT asm volatile("cp.async.commit_group;")
#define CP_WAIT1  asm volatile("cp.async.wait_group 1;")
#define CP_WAIT0  asm volatile("cp.async.wait_group 0;")

__device__ __forceinline__ float ex2f(float x) {
    float r; asm("ex2.approx.ftz.f32 %0, %1;" : "=f"(r) : "f"(x)); return r;
}
__device__ __forceinline__ uint32_t packbf(float f0, float f1) {  // {lo=f0, hi=f1}
    uint32_t r; asm("cvt.rn.bf16x2.f32 %0, %1, %2;" : "=r"(r) : "f"(f1), "f"(f0));
    return r;
}
__device__ __forceinline__ float truncbf(float v) {
    return __uint_as_float(__float_as_uint(v) & 0xFFFF0000u);
}
__device__ __forceinline__ __nv_bfloat16 bf_from_bits(uint32_t fb) {
    unsigned short us = (unsigned short)(fb >> 16);
    return *reinterpret_cast<__nv_bfloat16*>(&us);
}

// ---------------- kernel 1: build effective fused weights --------------------
__global__ void build_eff(const float* __restrict__ Wq, const float* __restrict__ bq,
                          const float* __restrict__ Wk, const float* __restrict__ bk,
                          const float* __restrict__ Wv, const float* __restrict__ bv,
                          const float* __restrict__ Wq_lsr, const float* __restrict__ Wk_lsr)
{
    int row = blockIdx.x;
    int tid = threadIdx.x;  // 256 threads

    if (row >= 1024) {
        int o = row - 1024;
        const float* src = Wv + (size_t)o * DM;
        float* dst = g_Weff + (size_t)row * DM;
        for (int d = tid; d < DM; d += 256) dst[d] = src[d];
        if (tid == 0) g_beff[row] = bv[o];
        return;
    }

    const float* W   = (row < 512) ? Wq : Wk;
    const float* bb  = (row < 512) ? bq : bk;
    const float* lsr = (row < 512) ? Wq_lsr : Wk_lsr;
    int rr = row & 511;
    int h  = rr >> 5;
    int r  = rr & 31;

    __shared__ float lcol[DH];
    if (tid < DH) lcol[tid] = lsr[(h * DH + tid) * RANK + r];
    __syncthreads();

    float* dst = g_Weff + (size_t)row * DM;
    for (int d = tid; d < DM; d += 256) {
        float s = 0.f;
        #pragma unroll
        for (int e = 0; e < DH; ++e)
            s += W[(size_t)(h * DH + e) * DM + d] * lcol[e];
        dst[d] = s;
    }
    if (tid == 0) {
        float s = 0.f;
        #pragma unroll
        for (int e = 0; e < DH; ++e) s += bb[h * DH + e] * lcol[e];
        g_beff[row] = s;
    }
}

// ---------------- split fp32 row (1024) -> bf16 row (3072) -------------------
__global__ __launch_bounds__(256)
void split3(const float* __restrict__ in, __nv_bfloat16* __restrict__ out, int pattern)
{
    int row = blockIdx.x;
    int tid = threadIdx.x;
    const float* ip = in + (size_t)row * DM;
    __nv_bfloat16* op = out + (size_t)row * K3;
    for (int d = tid; d < DM; d += 256) {
        float v = ip[d];
        __nv_bfloat16 hi = __float2bfloat16(v);
        __nv_bfloat16 lo = __float2bfloat16(v - __bfloat162float(hi));
        op[d] = hi;
        op[DM + d]     = pattern ? hi : lo;
        op[2 * DM + d] = pattern ? lo : hi;
    }
}

// ---------------- HMMA bf16 GEMM (unchanged from round 3) --------------------
__global__ __launch_bounds__(256)
void gemm_bf16_hmma(const __nv_bfloat16* __restrict__ A,
                    const __nv_bfloat16* __restrict__ B,
                    const float* __restrict__ bias,
                    float* __restrict__ C, int N)
{
    __shared__ __align__(128) char sm_tiles[2][2][8192];
    const uint32_t s_base = smem_to_u32(sm_tiles);

    const int tid  = threadIdx.x;
    const int lane = tid & 31;
    const int wid  = tid >> 5;
    const int wm   = wid >> 2;
    const int wn   = wid & 3;
    const int bm   = blockIdx.y * 128;
    const int bn   = blockIdx.x * 128;

    const __nv_bfloat16* Ab = A + (size_t)bm * K3;
    const __nv_bfloat16* Bb = B + (size_t)bn * K3;

    const int grow = tid >> 1;
    const int gseg = (tid & 1) * 2;
    const uint32_t sw0 = SW128((uint32_t)(grow * 64 + gseg * 16));
    const uint32_t sw1 = SW128((uint32_t)(grow * 64 + gseg * 16 + 16));
    const __nv_bfloat16* gA = Ab + (size_t)grow * K3 + gseg * 8;
    const __nv_bfloat16* gB = Bb + (size_t)grow * K3 + gseg * 8;

    uint32_t aoff[4][2], boff[2][2];
    #pragma unroll
    for (int f = 0; f < 4; ++f)
        #pragma unroll
        for (int ks = 0; ks < 2; ++ks)
            aoff[f][ks] = SW128((uint32_t)((wm * 64 + f * 16 + (lane & 15)) * 64 +
                                           (ks * 2 + (lane >> 4)) * 16));
    #pragma unroll
    for (int p = 0; p < 2; ++p)
        #pragma unroll
        for (int ks = 0; ks < 2; ++ks)
            boff[p][ks] = SW128((uint32_t)((wn * 32 + p * 16 + ((lane >> 4) & 1) * 8 +
                                            (lane & 7)) * 64 +
                                           (ks * 2 + ((lane >> 3) & 1)) * 16));

    float acc[4][4][4];
    #pragma unroll
    for (int f = 0; f < 4; ++f)
        #pragma unroll
        for (int nf = 0; nf < 4; ++nf)
            #pragma unroll
            for (int i = 0; i < 4; ++i) acc[f][nf][i] = 0.f;

    {
        uint4 a0 = *(const uint4*)(gA);
        uint4 a1 = *(const uint4*)(gA + 8);
        uint4 b0 = *(const uint4*)(gB);
        uint4 b1 = *(const uint4*)(gB + 8);
        char* sA = &sm_tiles[0][0][0];
        char* sB = &sm_tiles[0][1][0];
        *(uint4*)(sA + sw0) = a0; *(uint4*)(sA + sw1) = a1;
        *(uint4*)(sB + sw0) = b0; *(uint4*)(sB + sw1) = b1;
    }
    __syncthreads();

    for (int c = 0; c < NCH; ++c) {
        const int stg = c & 1;
        uint4 pa0, pa1, pb0, pb1;
        if (c + 1 < NCH) {
            const int ko = (c + 1) * KCH;
            pa0 = *(const uint4*)(gA + ko);
            pa1 = *(const uint4*)(gA + ko + 8);
            pb0 = *(const uint4*)(gB + ko);
            pb1 = *(const uint4*)(gB + ko + 8);
        }

        const uint32_t As = s_base + (uint32_t)stg * 16384u;
        const uint32_t Bs = As + 8192u;
        #pragma unroll
        for (int ks = 0; ks < 2; ++ks) {
            uint32_t a[4][4];
            #pragma unroll
            for (int f = 0; f < 4; ++f)
                LDMX4(a[f][0], a[f][1], a[f][2], a[f][3], As + aoff[f][ks]);
            uint32_t b[4][2];
            #pragma unroll
            for (int p = 0; p < 2; ++p)
                LDMX4(b[2 * p][0], b[2 * p][1], b[2 * p + 1][0], b[2 * p + 1][1],
                      Bs + boff[p][ks]);
            #pragma unroll
            for (int f = 0; f < 4; ++f)
                #pragma unroll
                for (int nf = 0; nf < 4; ++nf)
                    MMA16816(acc[f][nf], a[f], b[nf]);
        }

        if (c + 1 < NCH) {
            char* sA = &sm_tiles[(c + 1) & 1][0][0];
            char* sB = &sm_tiles[(c + 1) & 1][1][0];
            *(uint4*)(sA + sw0) = pa0; *(uint4*)(sA + sw1) = pa1;
            *(uint4*)(sB + sw0) = pb0; *(uint4*)(sB + sw1) = pb1;
        }
        __syncthreads();
    }

    const int col0 = bn + wn * 32 + (lane & 3) * 2;
    float2 blv[4];
    #pragma unroll
    for (int nf = 0; nf < 4; ++nf) {
        blv[nf].x = bias[col0 + nf * 8];
        blv[nf].y = bias[col0 + nf * 8 + 1];
    }
    #pragma unroll
    for (int f = 0; f < 4; ++f) {
        const int row = bm + wm * 64 + f * 16 + (lane >> 2);
        #pragma unroll
        for (int nf = 0; nf < 4; ++nf) {
            const int col = col0 + nf * 8;
            float2 o0 = make_float2(acc[f][nf][0] + blv[nf].x,
                                    acc[f][nf][1] + blv[nf].y);
            float2 o1 = make_float2(acc[f][nf][2] + blv[nf].x,
                                    acc[f][nf][3] + blv[nf].y);
            *(float2*)(C + (size_t)row * N + col)       = o0;
            *(float2*)(C + (size_t)(row + 8) * N + col) = o1;
        }
    }
}

// ---------------- attention prep: split qkv into q2/k2/vh/vl -----------------
__global__ __launch_bounds__(256)
void attn_prep()
{
    const int tg = blockIdx.x;           // global token [0, 8192)
    const int b  = tg >> 11;
    const int tt = tg & 2047;
    const int tid = threadIdx.x;
    const float* row = g_qkv + (size_t)tg * NQKV;
    const float qs = 1.44269504088896f * 0.1767766952966369f;  // log2e / sqrt(32)

    #pragma unroll
    for (int i = 0; i < 2; ++i) {        // q: 512 elems
        int idx = tid + i * 256;
        int h = idx >> 5, r = idx & 31;
        float v = row[h * 32 + r] * qs;
        uint32_t hb = __float_as_uint(v) & 0xFFFF0000u;
        size_t dst = ((size_t)(b * 16 + h) * T_SEQ + tt) * 64;
        g_q2[dst + r]      = bf_from_bits(hb);
        g_q2[dst + 32 + r] = __float2bfloat16(v - __uint_as_float(hb));
    }
    #pragma unroll
    for (int i = 0; i < 2; ++i) {        // k: 512 elems
        int idx = tid + i * 256;
        int h = idx >> 5, r = idx & 31;
        float v = row[512 + h * 32 + r];
        uint32_t hb = __float_as_uint(v) & 0xFFFF0000u;
        size_t dst = ((size_t)(b * 16 + h) * T_SEQ + tt) * 64;
        g_k2[dst + r]      = bf_from_bits(hb);
        g_k2[dst + 32 + r] = __float2bfloat16(v - __uint_as_float(hb));
    }
    #pragma unroll
    for (int i = 0; i < 4; ++i) {        // v: 1024 elems
        int idx = tid + i * 256;
        int h = idx >> 6, d = idx & 63;
        float v = row[1024 + h * 64 + d];
        uint32_t hb = __float_as_uint(v) & 0xFFFF0000u;
        size_t dst = ((size_t)(b * 16 + h) * T_SEQ + tt) * 64 + d;
        g_vh[dst] = bf_from_bits(hb);
        g_vl[dst] = __float2bfloat16(v - __uint_as_float(hb));
    }
}

// ---------------- HMMA flash attention ---------------------------------------
// CTA: 128 q rows, 8 warps (16 rows each), 64-key tiles, cp.async double buffer.
#define ATT_Q     16384
#define ATT_STAGE 24576
#define ATT_SMEM  (1024 + ATT_Q + 2 * ATT_STAGE)

__global__ __launch_bounds__(256)
void attn_mma()
{
    extern __shared__ char smraw[];
    const uint32_t smb0 = smem_to_u32(smraw);
    const uint32_t smb  = (smb0 + 1023u) & ~1023u;          // 1KB-aligned base
    char* smc = smraw + (smb - smb0);

    const int tid  = threadIdx.x;
    const int lane = tid & 31;
    const int w    = tid >> 5;
    const int qt   = (int)gridDim.x - 1 - (int)blockIdx.x;  // heavy tiles first
    const int bh   = blockIdx.y;
    const int qbase = qt * 128;
    const int njt   = qt * 2 + 2;
    const size_t tokb = (size_t)bh * T_SEQ;

    // ---- Q tile: direct loads into swizzled smem ----
    #pragma unroll
    for (int i = 0; i < 4; ++i) {
        int s = tid + i * 256;
        int r = s >> 3, c = s & 7;
        uint4 v = *(const uint4*)(g_q2 + (tokb + qbase + r) * 64 + c * 8);
        *(uint4*)(smc + SW128((uint32_t)(r * 128 + c * 16))) = v;
    }

    // ---- cp.async tile issue (K | Vhi | Vlo, 24KB per stage) ----
    auto issue = [&](int jt) {
        const int jb = jt * 64;
        const uint32_t stg = smb + ATT_Q + (uint32_t)(jt & 1) * ATT_STAGE;
        #pragma unroll
        for (int i = 0; i < 6; ++i) {
            int s = tid + i * 256;
            int tile = s >> 9;
            int ss = s & 511;
            int r = ss >> 3, c = ss & 7;
            const __nv_bfloat16* src =
                (tile == 0 ? g_k2 : (tile == 1 ? g_vh : g_vl)) +
                (tokb + jb + r) * 64 + c * 8;
            uint32_t dst = stg + (uint32_t)tile * 8192u +
                           SW128((uint32_t)(r * 128 + c * 16));
            CP16(dst, src);
        }
        CP_COMMIT;
    };

    issue(0);
    issue(1);
    __syncthreads();   // Q smem ready

    // ---- Q fragments (hi, lo), K=32 -> 2 ksteps ----
    uint32_t qh[2][4], ql[2][4];
    #pragma unroll
    for (int ks = 0; ks < 2; ++ks) {
        uint32_t rb = (uint32_t)((w * 16 + (lane & 15)) * 128);
        LDMX4(qh[ks][0], qh[ks][1], qh[ks][2], qh[ks][3],
              smb + SW128(rb + (uint32_t)(ks * 32 + (lane >> 4) * 16)));
        LDMX4(ql[ks][0], ql[ks][1], ql[ks][2], ql[ks][3],
              smb + SW128(rb + (uint32_t)(64 + ks * 32 + (lane >> 4) * 16)));
    }

    float m0 = -1e30f, m1 = -1e30f, l0 = 0.f, l1 = 0.f;
    float O[8][4];
    #pragma unroll
    for (int nf = 0; nf < 8; ++nf)
        #pragma unroll
        for (int i = 0; i < 4; ++i) O[nf][i] = 0.f;

    const int rowlo = qbase + w * 16;

    for (int jt = 0; jt < njt; ++jt) {
        if (jt + 1 < njt) { CP_WAIT1; } else { CP_WAIT0; }
        __syncthreads();
        const int jbase = jt * 64;
        const uint32_t Ks = smb + ATT_Q + (uint32_t)(jt & 1) * ATT_STAGE;
        const uint32_t Vh = Ks + 8192u, Vl = Ks + 16384u;

        if (jbase <= rowlo + 15) {                     // not fully above diagonal
            float S[8][4];
            #pragma unroll
            for (int nf = 0; nf < 8; ++nf)
                #pragma unroll
                for (int i = 0; i < 4; ++i) S[nf][i] = 0.f;

            // ---- S = Qhi*Khi + Qlo*Khi + Qhi*Klo ----
            #pragma unroll
            for (int ks = 0; ks < 2; ++ks) {
                uint32_t kb[8][2];
                #pragma unroll
                for (int p = 0; p < 4; ++p) {
                    uint32_t a = Ks + SW128((uint32_t)(
                        (p * 16 + ((lane >> 4) & 1) * 8 + (lane & 7)) * 128 +
                        ks * 32 + ((lane >> 3) & 1) * 16));
                    LDMX4(kb[2*p][0], kb[2*p][1], kb[2*p+1][0], kb[2*p+1][1], a);
                }
                #pragma unroll
                for (int nf = 0; nf < 8; ++nf) {
                    MMA16816(S[nf], qh[ks], kb[nf]);
                    MMA16816(S[nf], ql[ks], kb[nf]);
                }
                #pragma unroll
                for (int p = 0; p < 4; ++p) {
                    uint32_t a = Ks + SW128((uint32_t)(
                        (p * 16 + ((lane >> 4) & 1) * 8 + (lane & 7)) * 128 +
                        64 + ks * 32 + ((lane >> 3) & 1) * 16));
                    LDMX4(kb[2*p][0], kb[2*p][1], kb[2*p+1][0], kb[2*p+1][1], a);
                }
                #pragma unroll
                for (int nf = 0; nf < 8; ++nf)
                    MMA16816(S[nf], qh[ks], kb[nf]);
            }

            const int r0 = rowlo + (lane >> 2), r1 = r0 + 8;
            // ---- causal mask (diagonal tiles only) ----
            if (jbase + 63 > rowlo) {
                #pragma unroll
                for (int nf = 0; nf < 8; ++nf) {
                    int j0 = jbase + nf * 8 + (lane & 3) * 2;
                    if (j0     > r0) S[nf][0] = -1e30f;
                    if (j0 + 1 > r0) S[nf][1] = -1e30f;
                    if (j0     > r1) S[nf][2] = -1e30f;
                    if (j0 + 1 > r1) S[nf][3] = -1e30f;
                }
            }
            // ---- online softmax (log2 domain) ----
            float mx0 = S[0][0], mx1 = S[0][2];
            #pragma unroll
            for (int nf = 0; nf < 8; ++nf) {
                mx0 = fmaxf(mx0, fmaxf(S[nf][0], S[nf][1]));
                mx1 = fmaxf(mx1, fmaxf(S[nf][2], S[nf][3]));
            }
            mx0 = fmaxf(mx0, __shfl_xor_sync(0xffffffffu, mx0, 1));
            mx0 = fmaxf(mx0, __shfl_xor_sync(0xffffffffu, mx0, 2));
            mx1 = fmaxf(mx1, __shfl_xor_sync(0xffffffffu, mx1, 1));
            mx1 = fmaxf(mx1, __shfl_xor_sync(0xffffffffu, mx1, 2));
            float mn0 = fmaxf(m0, mx0), mn1 = fmaxf(m1, mx1);
            float sc0 = ex2f(m0 - mn0), sc1 = ex2f(m1 - mn1);
            m0 = mn0; m1 = mn1;
            l0 *= sc0; l1 *= sc1;
            #pragma unroll
            for (int nf = 0; nf < 8; ++nf) {
                O[nf][0] *= sc0; O[nf][1] *= sc0;
                O[nf][2] *= sc1; O[nf][3] *= sc1;
            }
            #pragma unroll
            for (int nf = 0; nf < 8; ++nf) {
                S[nf][0] = ex2f(S[nf][0] - m0); S[nf][1] = ex2f(S[nf][1] - m0);
                S[nf][2] = ex2f(S[nf][2] - m1); S[nf][3] = ex2f(S[nf][3] - m1);
                l0 += S[nf][0] + S[nf][1];
                l1 += S[nf][2] + S[nf][3];
            }
            // ---- O += Phi*Vhi + Plo*Vhi + Phi*Vlo ----
            #pragma unroll
            for (int ks = 0; ks < 4; ++ks) {
                uint32_t ah[4], al[4];
                {
                    float h00 = truncbf(S[2*ks][0]),   h01 = truncbf(S[2*ks][1]);
                    float h10 = truncbf(S[2*ks][2]),   h11 = truncbf(S[2*ks][3]);
                    float h20 = truncbf(S[2*ks+1][0]), h21 = truncbf(S[2*ks+1][1]);
                    float h30 = truncbf(S[2*ks+1][2]), h31 = truncbf(S[2*ks+1][3]);
                    ah[0] = packbf(h00, h01); al[0] = packbf(S[2*ks][0]-h00,   S[2*ks][1]-h01);
                    ah[1] = packbf(h10, h11); al[1] = packbf(S[2*ks][2]-h10,   S[2*ks][3]-h11);
                    ah[2] = packbf(h20, h21); al[2] = packbf(S[2*ks+1][0]-h20, S[2*ks+1][1]-h21);
                    ah[3] = packbf(h30, h31); al[3] = packbf(S[2*ks+1][2]-h30, S[2*ks+1][3]-h31);
                }
                const uint32_t rowb = (uint32_t)((ks * 16 + (lane & 15)) * 128);
                const uint32_t colb = (uint32_t)((lane >> 4) * 16);
                #pragma unroll
                for (int dp = 0; dp < 4; ++dp) {
                    uint32_t vb[4];
                    uint32_t sw = SW128(rowb + (uint32_t)(dp * 32) + colb);
                    LDMX4T(vb[0], vb[1], vb[2], vb[3], Vh + sw);
                    MMA16816(O[2*dp],     ah, vb);
                    MMA16816(O[2*dp],     al, vb);
                    MMA16816(O[2*dp + 1], ah, vb + 2);
                    MMA16816(O[2*dp + 1], al, vb + 2);
                    LDMX4T(vb[0], vb[1], vb[2], vb[3], Vl + sw);
                    MMA16816(O[2*dp],     ah, vb);
                    MMA16816(O[2*dp + 1], ah, vb + 2);
                }
            }
        }
        __syncthreads();
        if (jt + 2 < njt) issue(jt + 2);
    }

    // ---- epilogue: normalize, split to bf16 [hi|lo|hi], write y3 ----
    l0 += __shfl_xor_sync(0xffffffffu, l0, 1);
    l0 += __shfl_xor_sync(0xffffffffu, l0, 2);
    l1 += __shfl_xor_sync(0xffffffffu, l1, 1);
    l1 += __shfl_xor_sync(0xffffffffu, l1, 2);
    const float i0 = 1.f / l0, i1 = 1.f / l1;

    const int bb = bh >> 4, hh = bh & 15;
    const size_t t0 = (size_t)bb * T_SEQ + qbase + w * 16 + (lane >> 2);
    const size_t t1 = t0 + 8;
    const int colb = hh * 64 + (lane & 3) * 2;
    #pragma unroll
    for (int nf = 0; nf < 8; ++nf) {
        const int col = colb + nf * 8;
        {
            float v0 = O[nf][0] * i0, v1 = O[nf][1] * i0;
            float h0 = truncbf(v0), h1 = truncbf(v1);
            uint32_t hi = packbf(h0, h1), lo = packbf(v0 - h0, v1 - h1);
            *(uint32_t*)(g_a3 + t0 * K3 + col)        = hi;
            *(uint32_t*)(g_a3 + t0 * K3 + 1024 + col) = lo;
            *(uint32_t*)(g_a3 + t0 * K3 + 2048 + col) = hi;
        }
        {
            float v0 = O[nf][2] * i1, v1 = O[nf][3] * i1;
            float h0 = truncbf(v0), h1 = truncbf(v1);
            uint32_t hi = packbf(h0, h1), lo = packbf(v0 - h0, v1 - h1);
            *(uint32_t*)(g_a3 + t1 * K3 + col)        = hi;
            *(uint32_t*)(g_a3 + t1 * K3 + 1024 + col) = lo;
            *(uint32_t*)(g_a3 + t1 * K3 + 2048 + col) = hi;
        }
    }
}

// ---------------- launch ----------------
extern "C" void kernel_launch(void* const* d_in, const int* in_sizes, int n_in,
                              void* d_out, int out_size)
{
    const float* x      = (const float*)d_in[0];
    const float* Wq     = (const float*)d_in[1];
    const float* bq     = (const float*)d_in[2];
    const float* Wk     = (const float*)d_in[3];
    const float* bk     = (const float*)d_in[4];
    const float* Wv     = (const float*)d_in[5];
    const float* bv     = (const float*)d_in[6];
    const float* Wo     = (const float*)d_in[7];
    const float* bo     = (const float*)d_in[8];
    const float* Wq_lsr = (const float*)d_in[9];
    const float* Wk_lsr = (const float*)d_in[10];
    float* out = (float*)d_out;

    float *pWeff, *pbeff, *pqkv;
    __nv_bfloat16 *pa3, *pb3;
    cudaGetSymbolAddress((void**)&pWeff, g_Weff);
    cudaGetSymbolAddress((void**)&pbeff, g_beff);
    cudaGetSymbolAddress((void**)&pqkv,  g_qkv);
    cudaGetSymbolAddress((void**)&pa3,   g_a3);
    cudaGetSymbolAddress((void**)&pb3,   g_b3);

    cudaFuncSetAttribute(attn_mma,
                         cudaFuncAttributeMaxDynamicSharedMemorySize, ATT_SMEM);

    // 1) fused effective weights [Wq_eff | Wk_eff | Wv]
    build_eff<<<NQKV, 256>>>(Wq, bq, Wk, bk, Wv, bv, Wq_lsr, Wk_lsr);

    // 2) splits for qkv GEMM
    split3<<<M_TOK, 256>>>(x, pa3, 0);
    split3<<<NQKV, 256>>>(pWeff, pb3, 1);

    // 3) qkv = x @ Weff^T + beff (HMMA bf16 3x)
    gemm_bf16_hmma<<<dim3(NQKV / 128, M_TOK / 128), 256>>>(pa3, pb3, pbeff, pqkv, NQKV);

    // 4) split q/k/v into attention operands
    attn_prep<<<M_TOK, 256>>>();

    // 5) HMMA flash attention -> y3 (split form) in g_a3
    attn_mma<<<dim3(T_SEQ / 128, BATCH * NH), 256, ATT_SMEM>>>();

    // 6) split Wo
    split3<<<DM, 256>>>(Wo, pb3, 1);

    // 7) out = y @ Wo^T + bo (HMMA bf16 3x)
    gemm_bf16_hmma<<<dim3(DM / 128, M_TOK / 128), 256>>>(pa3, pb3, bo, out, DM);
}

// round 5
// speedup vs baseline: 3.3324x; 1.2977x over previous
#include <cuda_runtime.h>
#include <cuda_bf16.h>
#include <math.h>
#include <stdint.h>

#define T_SEQ  2048
#define BATCH  4
#define NH     16
#define DH     64
#define RANK   32
#define DM     1024
#define M_TOK  (BATCH * T_SEQ)   // 8192
#define NQKV   2048               // 512 q_lr | 512 k_lr | 1024 v
#define K3     (3 * DM)           // 3072 virtual K (hi/lo/hi split)

// ---------------- scratch (device globals; no allocs allowed) ----------------
__device__ float          g_Weff[(size_t)NQKV * DM];     // 8 MB
__device__ float          g_beff[NQKV];
__device__ float          g_qkv [(size_t)M_TOK * NQKV];  // 64 MB
__device__ __nv_bfloat16  g_a3  [(size_t)M_TOK * K3];    // 48 MB (x3, then y3)
__device__ __nv_bfloat16  g_b3  [(size_t)NQKV  * K3];    // 12 MB (Weff3, then Wo3)
// attention split operands, [bh][t][64] each (16 MB each)
__device__ __nv_bfloat16  g_q2 [(size_t)64 * T_SEQ * 64];
__device__ __nv_bfloat16  g_k2 [(size_t)64 * T_SEQ * 64];
__device__ __nv_bfloat16  g_vh [(size_t)64 * T_SEQ * 64];
__device__ __nv_bfloat16  g_vl [(size_t)64 * T_SEQ * 64];

// ============================ helpers ========================================
__device__ __forceinline__ uint32_t smem_to_u32(const void* p) {
    uint32_t a;
    asm("{ .reg .u64 t; cvta.to.shared.u64 t, %1; cvt.u32.u64 %0, t; }"
        : "=r"(a) : "l"(p));
    return a;
}
#define SW128(off) ((off) ^ (((off) >> 3) & 0x70))

#define LDMX4(r0, r1, r2, r3, addr) \
    asm volatile("ldmatrix.sync.aligned.m8n8.x4.shared.b16 {%0,%1,%2,%3}, [%4];" \
        : "=r"(r0), "=r"(r1), "=r"(r2), "=r"(r3) : "r"(addr))

#define LDMX4T(r0, r1, r2, r3, addr) \
    asm volatile("ldmatrix.sync.aligned.m8n8.x4.trans.shared.b16 {%0,%1,%2,%3}, [%4];" \
        : "=r"(r0), "=r"(r1), "=r"(r2), "=r"(r3) : "r"(addr))

#define MMA16816(c, a, b) \
    asm volatile("mma.sync.aligned.m16n8k16.row.col.f32.bf16.bf16.f32 " \
        "{%0,%1,%2,%3}, {%4,%5,%6,%7}, {%8,%9}, {%0,%1,%2,%3};" \
        : "+f"((c)[0]), "+f"((c)[1]), "+f"((c)[2]), "+f"((c)[3]) \
        : "r"((a)[0]), "r"((a)[1]), "r"((a)[2]), "r"((a)[3]), \
          "r"((b)[0]), "r"((b)[1]))

#define CP16(dst, src) \
    asm volatile("cp.async.cg.shared.global [%0], [%1], 16;" :: "r"(dst), "l"(src))
#define CP_COMMIT asm volatile("cp.async.commit_group;")
#define CP_WAIT1  asm volatile("cp.async.wait_group 1;")
#define CP_WAIT0  asm volatile("cp.async.wait_group 0;")

__device__ __forceinline__ float ex2f(float x) {
    float r; asm("ex2.approx.ftz.f32 %0, %1;" : "=f"(r) : "f"(x)); return r;
}
__device__ __forceinline__ uint32_t packbf(float f0, float f1) {  // {lo=f0, hi=f1}
    uint32_t r; asm("cvt.rn.bf16x2.f32 %0, %1, %2;" : "=r"(r) : "f"(f1), "f"(f0));
    return r;
}
__device__ __forceinline__ float truncbf(float v) {
    return __uint_as_float(__float_as_uint(v) & 0xFFFF0000u);
}
__device__ __forceinline__ __nv_bfloat16 bf_from_bits(uint32_t fb) {
    unsigned short us = (unsigned short)(fb >> 16);
    return *reinterpret_cast<__nv_bfloat16*>(&us);
}

// ---------------- kernel 1: build effective fused weights --------------------
__global__ void build_eff(const float* __restrict__ Wq, const float* __restrict__ bq,
                          const float* __restrict__ Wk, const float* __restrict__ bk,
                          const float* __restrict__ Wv, const float* __restrict__ bv,
                          const float* __restrict__ Wq_lsr, const float* __restrict__ Wk_lsr)
{
    int row = blockIdx.x;
    int tid = threadIdx.x;  // 256 threads

    if (row >= 1024) {
        int o = row - 1024;
        const float* src = Wv + (size_t)o * DM;
        float* dst = g_Weff + (size_t)row * DM;
        for (int d = tid; d < DM; d += 256) dst[d] = src[d];
        if (tid == 0) g_beff[row] = bv[o];
        return;
    }

    const float* W   = (row < 512) ? Wq : Wk;
    const float* bb  = (row < 512) ? bq : bk;
    const float* lsr = (row < 512) ? Wq_lsr : Wk_lsr;
    int rr = row & 511;
    int h  = rr >> 5;
    int r  = rr & 31;

    __shared__ float lcol[DH];
    if (tid < DH) lcol[tid] = lsr[(h * DH + tid) * RANK + r];
    __syncthreads();

    float* dst = g_Weff + (size_t)row * DM;
    for (int d = tid; d < DM; d += 256) {
        float s = 0.f;
        #pragma unroll
        for (int e = 0; e < DH; ++e)
            s += W[(size_t)(h * DH + e) * DM + d] * lcol[e];
        dst[d] = s;
    }
    if (tid == 0) {
        float s = 0.f;
        #pragma unroll
        for (int e = 0; e < DH; ++e) s += bb[h * DH + e] * lcol[e];
        g_beff[row] = s;
    }
}

// ---------------- split fp32 row (1024) -> bf16 row (3072) -------------------
__global__ __launch_bounds__(256)
void split3(const float* __restrict__ in, __nv_bfloat16* __restrict__ out, int pattern)
{
    int row = blockIdx.x;
    int tid = threadIdx.x;
    const float* ip = in + (size_t)row * DM;
    __nv_bfloat16* op = out + (size_t)row * K3;
    for (int d = tid; d < DM; d += 256) {
        float v = ip[d];
        __nv_bfloat16 hi = __float2bfloat16(v);
        __nv_bfloat16 lo = __float2bfloat16(v - __bfloat162float(hi));
        op[d] = hi;
        op[DM + d]     = pattern ? hi : lo;
        op[2 * DM + d] = pattern ? lo : hi;
    }
}

// ---------------- HMMA bf16 GEMM v2: cp.async 3-stage, BK=64, 4 warps --------
// CTA 128x128, warps 2(M)x2(N), warp tile 64x64, 128B SW128 smem rows.
#define KCH2    64
#define NCH2    (K3 / KCH2)       // 48
#define GTILE_A 16384              // 128 rows x 128B
#define GSTAGE  (2 * GTILE_A)      // A+B = 32 KB
#define GSMEM   (3 * GSTAGE)       // 96 KB

__global__ __launch_bounds__(128)
void gemm_bf16_v2(const __nv_bfloat16* __restrict__ A,
                  const __nv_bfloat16* __restrict__ B,
                  const float* __restrict__ bias,
                  float* __restrict__ C, int N)
{
    extern __shared__ char gsm[];
    const uint32_t smb = smem_to_u32(gsm);

    const int tid  = threadIdx.x;
    const int lane = tid & 31;
    const int w    = tid >> 5;
    const int wm   = w >> 1;      // 0..1
    const int wn   = w & 1;       // 0..1
    const int bm   = blockIdx.y * 128;
    const int bn   = blockIdx.x * 128;

    const __nv_bfloat16* Ab = A + (size_t)bm * K3;
    const __nv_bfloat16* Bb = B + (size_t)bn * K3;

    // cp.async mapping: 1024 x 16B segments per tile, 128 threads x 8
    const int crow = tid >> 3;          // base row pattern piece
    const int cseg = tid & 7;

    // ---- ldmatrix address components ----
    // A: row = wm*64 + f*16 + (lane&15); cb = ks*32 + (lane>>4)*16
    uint32_t abase[4], arx[4];
    #pragma unroll
    for (int f = 0; f < 4; ++f) {
        int row = wm * 64 + f * 16 + (lane & 15);
        abase[f] = (uint32_t)(row * 128);
        arx[f]   = (uint32_t)((row & 7) << 4);
    }
    const uint32_t acb0 = (uint32_t)((lane >> 4) * 16);
    // B: row = wn*64 + p*16 + ((lane>>4)&1)*8 + (lane&7); cb = ks*32 + ((lane>>3)&1)*16
    uint32_t bbase[4], brx[4];
    #pragma unroll
    for (int p = 0; p < 4; ++p) {
        int row = wn * 64 + p * 16 + ((lane >> 4) & 1) * 8 + (lane & 7);
        bbase[p] = (uint32_t)(row * 128);
        brx[p]   = (uint32_t)((row & 7) << 4);
    }
    const uint32_t bcb0 = (uint32_t)(((lane >> 3) & 1) * 16);

    float acc[4][8][4];
    #pragma unroll
    for (int f = 0; f < 4; ++f)
        #pragma unroll
        for (int nf = 0; nf < 8; ++nf)
            #pragma unroll
            for (int i = 0; i < 4; ++i) acc[f][nf][i] = 0.f;

    auto issue = [&](int c) {
        const uint32_t stg = smb + (uint32_t)(c % 3) * GSTAGE;
        const int ko = c * KCH2;
        #pragma unroll
        for (int i = 0; i < 8; ++i) {
            int r = crow + i * 16;
            uint32_t sw = SW128((uint32_t)(r * 128 + cseg * 16));
            CP16(stg + sw,           Ab + (size_t)r * K3 + ko + cseg * 8);
            CP16(stg + GTILE_A + sw, Bb + (size_t)r * K3 + ko + cseg * 8);
        }
        CP_COMMIT;
    };

    issue(0);
    issue(1);

    for (int c = 0; c < NCH2; ++c) {
        if (c + 1 < NCH2) { CP_WAIT1; } else { CP_WAIT0; }
        __syncthreads();
        if (c + 2 < NCH2) issue(c + 2);

        const uint32_t As = smb + (uint32_t)(c % 3) * GSTAGE;
        const uint32_t Bs = As + GTILE_A;

        #pragma unroll
        for (int ks = 0; ks < 4; ++ks) {
            uint32_t a[4][4];
            #pragma unroll
            for (int f = 0; f < 4; ++f)
                LDMX4(a[f][0], a[f][1], a[f][2], a[f][3],
                      As + abase[f] + (((acb0 | (uint32_t)(ks << 5))) ^ arx[f]));
            uint32_t b[8][2];
            #pragma unroll
            for (int p = 0; p < 4; ++p)
                LDMX4(b[2*p][0], b[2*p][1], b[2*p+1][0], b[2*p+1][1],
                      Bs + bbase[p] + (((bcb0 | (uint32_t)(ks << 5))) ^ brx[p]));
            #pragma unroll
            for (int f = 0; f < 4; ++f)
                #pragma unroll
                for (int nf = 0; nf < 8; ++nf)
                    MMA16816(acc[f][nf], a[f], b[nf]);
        }
        __syncthreads();
    }

    // ---- epilogue: bias + store ----
    const int col0 = bn + wn * 64 + (lane & 3) * 2;
    #pragma unroll
    for (int f = 0; f < 4; ++f) {
        const int row = bm + wm * 64 + f * 16 + (lane >> 2);
        #pragma unroll
        for (int nf = 0; nf < 8; ++nf) {
            const int col = col0 + nf * 8;
            const float b0 = bias[col], b1 = bias[col + 1];
            float2 o0 = make_float2(acc[f][nf][0] + b0, acc[f][nf][1] + b1);
            float2 o1 = make_float2(acc[f][nf][2] + b0, acc[f][nf][3] + b1);
            *(float2*)(C + (size_t)row * N + col)       = o0;
            *(float2*)(C + (size_t)(row + 8) * N + col) = o1;
        }
    }
}

// ---------------- attention prep: split qkv into q2/k2/vh/vl -----------------
__global__ __launch_bounds__(256)
void attn_prep()
{
    const int tg = blockIdx.x;           // global token [0, 8192)
    const int b  = tg >> 11;
    const int tt = tg & 2047;
    const int tid = threadIdx.x;
    const float* row = g_qkv + (size_t)tg * NQKV;
    const float qs = 1.44269504088896f * 0.1767766952966369f;  // log2e / sqrt(32)

    #pragma unroll
    for (int i = 0; i < 2; ++i) {        // q: 512 elems
        int idx = tid + i * 256;
        int h = idx >> 5, r = idx & 31;
        float v = row[h * 32 + r] * qs;
        uint32_t hb = __float_as_uint(v) & 0xFFFF0000u;
        size_t dst = ((size_t)(b * 16 + h) * T_SEQ + tt) * 64;
        g_q2[dst + r]      = bf_from_bits(hb);
        g_q2[dst + 32 + r] = __float2bfloat16(v - __uint_as_float(hb));
    }
    #pragma unroll
    for (int i = 0; i < 2; ++i) {        // k: 512 elems
        int idx = tid + i * 256;
        int h = idx >> 5, r = idx & 31;
        float v = row[512 + h * 32 + r];
        uint32_t hb = __float_as_uint(v) & 0xFFFF0000u;
        size_t dst = ((size_t)(b * 16 + h) * T_SEQ + tt) * 64;
        g_k2[dst + r]      = bf_from_bits(hb);
        g_k2[dst + 32 + r] = __float2bfloat16(v - __uint_as_float(hb));
    }
    #pragma unroll
    for (int i = 0; i < 4; ++i) {        // v: 1024 elems
        int idx = tid + i * 256;
        int h = idx >> 6, d = idx & 63;
        float v = row[1024 + h * 64 + d];
        uint32_t hb = __float_as_uint(v) & 0xFFFF0000u;
        size_t dst = ((size_t)(b * 16 + h) * T_SEQ + tt) * 64 + d;
        g_vh[dst] = bf_from_bits(hb);
        g_vl[dst] = __float2bfloat16(v - __uint_as_float(hb));
    }
}

// ---------------- HMMA flash attention ---------------------------------------
#define ATT_Q     16384
#define ATT_STAGE 24576
#define ATT_SMEM  (1024 + ATT_Q + 2 * ATT_STAGE)

__global__ __launch_bounds__(256)
void attn_mma()
{
    extern __shared__ char smraw[];
    const uint32_t smb0 = smem_to_u32(smraw);
    const uint32_t smb  = (smb0 + 1023u) & ~1023u;
    char* smc = smraw + (smb - smb0);

    const int tid  = threadIdx.x;
    const int lane = tid & 31;
    const int w    = tid >> 5;
    const int qt   = (int)gridDim.x - 1 - (int)blockIdx.x;
    const int bh   = blockIdx.y;
    const int qbase = qt * 128;
    const int njt   = qt * 2 + 2;
    const size_t tokb = (size_t)bh * T_SEQ;

    #pragma unroll
    for (int i = 0; i < 4; ++i) {
        int s = tid + i * 256;
        int r = s >> 3, c = s & 7;
        uint4 v = *(const uint4*)(g_q2 + (tokb + qbase + r) * 64 + c * 8);
        *(uint4*)(smc + SW128((uint32_t)(r * 128 + c * 16))) = v;
    }

    auto issue = [&](int jt) {
        const int jb = jt * 64;
        const uint32_t stg = smb + ATT_Q + (uint32_t)(jt & 1) * ATT_STAGE;
        #pragma unroll
        for (int i = 0; i < 6; ++i) {
            int s = tid + i * 256;
            int tile = s >> 9;
            int ss = s & 511;
            int r = ss >> 3, c = ss & 7;
            const __nv_bfloat16* src =
                (tile == 0 ? g_k2 : (tile == 1 ? g_vh : g_vl)) +
                (tokb + jb + r) * 64 + c * 8;
            uint32_t dst = stg + (uint32_t)tile * 8192u +
                           SW128((uint32_t)(r * 128 + c * 16));
            CP16(dst, src);
        }
        CP_COMMIT;
    };

    issue(0);
    issue(1);
    __syncthreads();

    uint32_t qh[2][4], ql[2][4];
    #pragma unroll
    for (int ks = 0; ks < 2; ++ks) {
        uint32_t rb = (uint32_t)((w * 16 + (lane & 15)) * 128);
        LDMX4(qh[ks][0], qh[ks][1], qh[ks][2], qh[ks][3],
              smb + SW128(rb + (uint32_t)(ks * 32 + (lane >> 4) * 16)));
        LDMX4(ql[ks][0], ql[ks][1], ql[ks][2], ql[ks][3],
              smb + SW128(rb + (uint32_t)(64 + ks * 32 + (lane >> 4) * 16)));
    }

    float m0 = -1e30f, m1 = -1e30f, l0 = 0.f, l1 = 0.f;
    float O[8][4];
    #pragma unroll
    for (int nf = 0; nf < 8; ++nf)
        #pragma unroll
        for (int i = 0; i < 4; ++i) O[nf][i] = 0.f;

    const int rowlo = qbase + w * 16;

    for (int jt = 0; jt < njt; ++jt) {
        if (jt + 1 < njt) { CP_WAIT1; } else { CP_WAIT0; }
        __syncthreads();
        const int jbase = jt * 64;
        const uint32_t Ks = smb + ATT_Q + (uint32_t)(jt & 1) * ATT_STAGE;
        const uint32_t Vh = Ks + 8192u, Vl = Ks + 16384u;

        if (jbase <= rowlo + 15) {
            float S[8][4];
            #pragma unroll
            for (int nf = 0; nf < 8; ++nf)
                #pragma unroll
                for (int i = 0; i < 4; ++i) S[nf][i] = 0.f;

            #pragma unroll
            for (int ks = 0; ks < 2; ++ks) {
                uint32_t kb[8][2];
                #pragma unroll
                for (int p = 0; p < 4; ++p) {
                    uint32_t a = Ks + SW128((uint32_t)(
                        (p * 16 + ((lane >> 4) & 1) * 8 + (lane & 7)) * 128 +
                        ks * 32 + ((lane >> 3) & 1) * 16));
                    LDMX4(kb[2*p][0], kb[2*p][1], kb[2*p+1][0], kb[2*p+1][1], a);
                }
                #pragma unroll
                for (int nf = 0; nf < 8; ++nf) {
                    MMA16816(S[nf], qh[ks], kb[nf]);
                    MMA16816(S[nf], ql[ks], kb[nf]);
                }
                #pragma unroll
                for (int p = 0; p < 4; ++p) {
                    uint32_t a = Ks + SW128((uint32_t)(
                        (p * 16 + ((lane >> 4) & 1) * 8 + (lane & 7)) * 128 +
                        64 + ks * 32 + ((lane >> 3) & 1) * 16));
                    LDMX4(kb[2*p][0], kb[2*p][1], kb[2*p+1][0], kb[2*p+1][1], a);
                }
                #pragma unroll
                for (int nf = 0; nf < 8; ++nf)
                    MMA16816(S[nf], qh[ks], kb[nf]);
            }

            const int r0 = rowlo + (lane >> 2), r1 = r0 + 8;
            if (jbase + 63 > rowlo) {
                #pragma unroll
                for (int nf = 0; nf < 8; ++nf) {
                    int j0 = jbase + nf * 8 + (lane & 3) * 2;
                    if (j0     > r0) S[nf][0] = -1e30f;
                    if (j0 + 1 > r0) S[nf][1] = -1e30f;
                    if (j0     > r1) S[nf][2] = -1e30f;
                    if (j0 + 1 > r1) S[nf][3] = -1e30f;
                }
            }
            float mx0 = S[0][0], mx1 = S[0][2];
            #pragma unroll
            for (int nf = 0; nf < 8; ++nf) {
                mx0 = fmaxf(mx0, fmaxf(S[nf][0], S[nf][1]));
                mx1 = fmaxf(mx1, fmaxf(S[nf][2], S[nf][3]));
            }
            mx0 = fmaxf(mx0, __shfl_xor_sync(0xffffffffu, mx0, 1));
            mx0 = fmaxf(mx0, __shfl_xor_sync(0xffffffffu, mx0, 2));
            mx1 = fmaxf(mx1, __shfl_xor_sync(0xffffffffu, mx1, 1));
            mx1 = fmaxf(mx1, __shfl_xor_sync(0xffffffffu, mx1, 2));
            float mn0 = fmaxf(m0, mx0), mn1 = fmaxf(m1, mx1);
            float sc0 = ex2f(m0 - mn0), sc1 = ex2f(m1 - mn1);
            m0 = mn0; m1 = mn1;
            l0 *= sc0; l1 *= sc1;
            #pragma unroll
            for (int nf = 0; nf < 8; ++nf) {
                O[nf][0] *= sc0; O[nf][1] *= sc0;
                O[nf][2] *= sc1; O[nf][3] *= sc1;
            }
            #pragma unroll
            for (int nf = 0; nf < 8; ++nf) {
                S[nf][0] = ex2f(S[nf][0] - m0); S[nf][1] = ex2f(S[nf][1] - m0);
                S[nf][2] = ex2f(S[nf][2] - m1); S[nf][3] = ex2f(S[nf][3] - m1);
                l0 += S[nf][0] + S[nf][1];
                l1 += S[nf][2] + S[nf][3];
            }
            #pragma unroll
            for (int ks = 0; ks < 4; ++ks) {
                uint32_t ah[4], al[4];
                {
                    float h00 = truncbf(S[2*ks][0]),   h01 = truncbf(S[2*ks][1]);
                    float h10 = truncbf(S[2*ks][2]),   h11 = truncbf(S[2*ks][3]);
                    float h20 = truncbf(S[2*ks+1][0]), h21 = truncbf(S[2*ks+1][1]);
                    float h30 = truncbf(S[2*ks+1][2]), h31 = truncbf(S[2*ks+1][3]);
                    ah[0] = packbf(h00, h01); al[0] = packbf(S[2*ks][0]-h00,   S[2*ks][1]-h01);
                    ah[1] = packbf(h10, h11); al[1] = packbf(S[2*ks][2]-h10,   S[2*ks][3]-h11);
                    ah[2] = packbf(h20, h21); al[2] = packbf(S[2*ks+1][0]-h20, S[2*ks+1][1]-h21);
                    ah[3] = packbf(h30, h31); al[3] = packbf(S[2*ks+1][2]-h30, S[2*ks+1][3]-h31);
                }
                const uint32_t rowb = (uint32_t)((ks * 16 + (lane & 15)) * 128);
                const uint32_t colb = (uint32_t)((lane >> 4) * 16);
                #pragma unroll
                for (int dp = 0; dp < 4; ++dp) {
                    uint32_t vb[4];
                    uint32_t sw = SW128(rowb + (uint32_t)(dp * 32) + colb);
                    LDMX4T(vb[0], vb[1], vb[2], vb[3], Vh + sw);
                    MMA16816(O[2*dp],     ah, vb);
                    MMA16816(O[2*dp],     al, vb);
                    MMA16816(O[2*dp + 1], ah, vb + 2);
                    MMA16816(O[2*dp + 1], al, vb + 2);
                    LDMX4T(vb[0], vb[1], vb[2], vb[3], Vl + sw);
                    MMA16816(O[2*dp],     ah, vb);
                    MMA16816(O[2*dp + 1], ah, vb + 2);
                }
            }
        }
        __syncthreads();
        if (jt + 2 < njt) issue(jt + 2);
    }

    l0 += __shfl_xor_sync(0xffffffffu, l0, 1);
    l0 += __shfl_xor_sync(0xffffffffu, l0, 2);
    l1 += __shfl_xor_sync(0xffffffffu, l1, 1);
    l1 += __shfl_xor_sync(0xffffffffu, l1, 2);
    const float i0 = 1.f / l0, i1 = 1.f / l1;

    const int bb = bh >> 4, hh = bh & 15;
    const size_t t0 = (size_t)bb * T_SEQ + qbase + w * 16 + (lane >> 2);
    const size_t t1 = t0 + 8;
    const int colb = hh * 64 + (lane & 3) * 2;
    #pragma unroll
    for (int nf = 0; nf < 8; ++nf) {
        const int col = colb + nf * 8;
        {
            float v0 = O[nf][0] * i0, v1 = O[nf][1] * i0;
            float h0 = truncbf(v0), h1 = truncbf(v1);
            uint32_t hi = packbf(h0, h1), lo = packbf(v0 - h0, v1 - h1);
            *(uint32_t*)(g_a3 + t0 * K3 + col)        = hi;
            *(uint32_t*)(g_a3 + t0 * K3 + 1024 + col) = lo;
            *(uint32_t*)(g_a3 + t0 * K3 + 2048 + col) = hi;
        }
        {
            float v0 = O[nf][2] * i1, v1 = O[nf][3] * i1;
            float h0 = truncbf(v0), h1 = truncbf(v1);
            uint32_t hi = packbf(h0, h1), lo = packbf(v0 - h0, v1 - h1);
            *(uint32_t*)(g_a3 + t1 * K3 + col)        = hi;
            *(uint32_t*)(g_a3 + t1 * K3 + 1024 + col) = lo;
            *(uint32_t*)(g_a3 + t1 * K3 + 2048 + col) = hi;
        }
    }
}

// ---------------- launch ----------------
extern "C" void kernel_launch(void* const* d_in, const int* in_sizes, int n_in,
                              void* d_out, int out_size)
{
    const float* x      = (const float*)d_in[0];
    const float* Wq     = (const float*)d_in[1];
    const float* bq     = (const float*)d_in[2];
    const float* Wk     = (const float*)d_in[3];
    const float* bk     = (const float*)d_in[4];
    const float* Wv     = (const float*)d_in[5];
    const float* bv     = (const float*)d_in[6];
    const float* Wo     = (const float*)d_in[7];
    const float* bo     = (const float*)d_in[8];
    const float* Wq_lsr = (const float*)d_in[9];
    const float* Wk_lsr = (const float*)d_in[10];
    float* out = (float*)d_out;

    float *pWeff, *pbeff, *pqkv;
    __nv_bfloat16 *pa3, *pb3;
    cudaGetSymbolAddress((void**)&pWeff, g_Weff);
    cudaGetSymbolAddress((void**)&pbeff, g_beff);
    cudaGetSymbolAddress((void**)&pqkv,  g_qkv);
    cudaGetSymbolAddress((void**)&pa3,   g_a3);
    cudaGetSymbolAddress((void**)&pb3,   g_b3);

    cudaFuncSetAttribute(attn_mma,
                         cudaFuncAttributeMaxDynamicSharedMemorySize, ATT_SMEM);
    cudaFuncSetAttribute(gemm_bf16_v2,
                         cudaFuncAttributeMaxDynamicSharedMemorySize, GSMEM);

    // 1) fused effective weights [Wq_eff | Wk_eff | Wv]
    build_eff<<<NQKV, 256>>>(Wq, bq, Wk, bk, Wv, bv, Wq_lsr, Wk_lsr);

    // 2) splits for qkv GEMM
    split3<<<M_TOK, 256>>>(x, pa3, 0);
    split3<<<NQKV, 256>>>(pWeff, pb3, 1);

    // 3) qkv = x @ Weff^T + beff (HMMA bf16 3x, cp.async pipeline)
    gemm_bf16_v2<<<dim3(NQKV / 128, M_TOK / 128), 128, GSMEM>>>(
        pa3, pb3, pbeff, pqkv, NQKV);

    // 4) split q/k/v into attention operands
    attn_prep<<<M_TOK, 256>>>();

    // 5) HMMA flash attention -> y3 (split form) in g_a3
    attn_mma<<<dim3(T_SEQ / 128, BATCH * NH), 256, ATT_SMEM>>>();

    // 6) split Wo
    split3<<<DM, 256>>>(Wo, pb3, 1);

    // 7) out = y @ Wo^T + bo (HMMA bf16 3x, cp.async pipeline)
    gemm_bf16_v2<<<dim3(DM / 128, M_TOK / 128), 128, GSMEM>>>(
        pa3, pb3, bo, out, DM);
}